// round 4
// baseline (speedup 1.0000x reference)
#include <cuda_runtime.h>

#define BB 256
#define TT 2048
#define VV 128
#define CC 512
#define KK 10
#define CHUNK 256   // rows of onehots per block

// Fully fused: per-block params GEMM (redundant per b, L2-resident W),
// phi, and phi-weighted onehot reduction.
// grid = (T/CHUNK, B), 256 threads.
__global__ void __launch_bounds__(256)
k_fused(const float* __restrict__ x,
        const float* __restrict__ kap_old,
        const float4* __restrict__ oh,
        const float* __restrict__ W,
        const float* __restrict__ bias,
        float* __restrict__ w,
        float* __restrict__ out_kappa,
        float* __restrict__ p_out) {
    __shared__ float sp[3 * KK];   // [0,K): alpha  [K,2K): beta  [2K,3K): kappa
    __shared__ float s_phi[CHUNK];
    __shared__ float4 red[8][32];

    const int b = blockIdx.y;
    const int t0 = blockIdx.x * CHUNK;
    const int tid = threadIdx.x;
    const int lane = tid & 31, wid = tid >> 5;

    // ---- params: 30 dot products (x[b,:] . W[j,:]) over 8 warps ----
    const float4* xr = (const float4*)(x + b * CC);
    for (int j = wid; j < 3 * KK; j += 8) {
        const float4* wr = (const float4*)(W + j * CC);
        float s = 0.0f;
#pragma unroll
        for (int i = 0; i < 4; i++) {
            const float4 a = xr[i * 32 + lane];
            const float4 v = wr[i * 32 + lane];
            s += a.x * v.x + a.y * v.y + a.z * v.z + a.w * v.w;
        }
#pragma unroll
        for (int o = 16; o; o >>= 1) s += __shfl_down_sync(0xffffffffu, s, o);
        if (lane == 0) {
            float p = __expf(s + bias[j]);
            if (j >= 2 * KK) p += kap_old[b * KK + (j - 2 * KK)];  // kappa
            sp[j] = p;
        }
    }
    __syncthreads();

    // kappa output, once per b
    if (blockIdx.x == 0 && tid < KK) out_kappa[b * KK + tid] = sp[2 * KK + tid];

    // ---- phi[b, t0 + tid] ----
    {
        const float tf = (float)(t0 + tid);
        float s = 0.0f;
#pragma unroll
        for (int k = 0; k < KK; k++) {
            const float d = sp[2 * KK + k] - tf;
            s += sp[k] * __expf(-sp[KK + k] * d * d);
        }
        s_phi[tid] = s;
        __stcs(p_out + b * TT + t0 + tid, s);
    }
    __syncthreads();

    // ---- stream CHUNK x 128 of onehots, phi-weighted reduce ----
    const int q = tid & 31, r = tid >> 5;
    const float4* base = oh + (size_t)(b * TT + t0) * 32;  // 32 float4/row

    float4 acc = make_float4(0.f, 0.f, 0.f, 0.f);
#pragma unroll 8
    for (int i = 0; i < CHUNK / 8; i++) {
        const int idx = i * 256 + tid;           // row = i*8 + r, col = q
        const float4 o = __ldcs(base + idx);
        const float ph = s_phi[i * 8 + r];
        acc.x += ph * o.x;
        acc.y += ph * o.y;
        acc.z += ph * o.z;
        acc.w += ph * o.w;
    }

    red[r][q] = acc;
    __syncthreads();
    if (r < 4) {
        const float4 o = red[r + 4][q];
        acc.x += o.x; acc.y += o.y; acc.z += o.z; acc.w += o.w;
        red[r][q] = acc;
    }
    __syncthreads();
    if (r < 2) {
        const float4 o = red[r + 2][q];
        acc.x += o.x; acc.y += o.y; acc.z += o.z; acc.w += o.w;
        red[r][q] = acc;
    }
    __syncthreads();
    if (r == 0) {
        const float4 o = red[1][q];
        acc.x += o.x; acc.y += o.y; acc.z += o.z; acc.w += o.w;
        float* dst = w + b * VV + q * 4;
        atomicAdd(dst + 0, acc.x);
        atomicAdd(dst + 1, acc.y);
        atomicAdd(dst + 2, acc.z);
        atomicAdd(dst + 3, acc.w);
    }
}

extern "C" void kernel_launch(void* const* d_in, const int* in_sizes, int n_in,
                              void* d_out, int out_size) {
    const float* x        = (const float*)d_in[0];  // (B, C)
    const float* kap_old  = (const float*)d_in[1];  // (B, K)
    const float* onehots  = (const float*)d_in[2];  // (B, T, V)
    const float* W        = (const float*)d_in[3];  // (3K, C)
    const float* bias     = (const float*)d_in[4];  // (3K,)

    float* out   = (float*)d_out;
    float* w_out = out;                       // (B, V)
    float* k_out = out + BB * VV;             // (B, K)
    float* p_out = out + BB * VV + BB * KK;   // (B, T)

    // zero the atomic target (d_out is poisoned); capturable memset node
    cudaMemsetAsync(w_out, 0, BB * VV * sizeof(float));

    k_fused<<<dim3(TT / CHUNK, BB), 256>>>(x, kap_old, (const float4*)onehots,
                                           W, bias, w_out, k_out, p_out);
}

// round 5
// speedup vs baseline: 1.1840x; 1.1840x over previous
#include <cuda_runtime.h>

#define BB 256
#define TT 2048
#define VV 128
#define CC 512
#define KK 10
#define CHUNK 256   // rows of onehots per block in k_w

// scratch (no device allocs allowed)
__device__ float g_alpha[BB * KK];
__device__ float g_beta[BB * KK];
__device__ float g_kappa[BB * KK];

// -------- Kernel 1: params GEMM, one warp per (b, j); also zeroes w --------
__global__ void k_params(const float* __restrict__ x,
                         const float* __restrict__ kap_old,
                         const float* __restrict__ W,
                         const float* __restrict__ bias,
                         float* __restrict__ out_w,
                         float* __restrict__ out_kappa) {
    const int tid = threadIdx.x;
    const int gtid = blockIdx.x * blockDim.x + tid;

    if (gtid < BB * VV) out_w[gtid] = 0.0f;   // d_out poisoned; atomics target

    const int gw = gtid >> 5;
    const int lane = tid & 31;
    if (gw < BB * 3 * KK) {
        const int b = gw / (3 * KK);
        const int j = gw % (3 * KK);

        const float4* xr = (const float4*)(x + b * CC);
        const float4* wr = (const float4*)(W + j * CC);
        float s = 0.0f;
#pragma unroll
        for (int i = 0; i < 4; i++) {
            const float4 a = xr[i * 32 + lane];
            const float4 v = wr[i * 32 + lane];
            s += a.x * v.x + a.y * v.y + a.z * v.z + a.w * v.w;
        }
#pragma unroll
        for (int o = 16; o; o >>= 1) s += __shfl_down_sync(0xffffffffu, s, o);

        if (lane == 0) {
            const float p = __expf(s + bias[j]);
            if (j < KK) {
                g_alpha[b * KK + j] = p;
            } else if (j < 2 * KK) {
                g_beta[b * KK + (j - KK)] = p;
            } else {
                const int k = j - 2 * KK;
                const float kp = kap_old[b * KK + k] + p;
                g_kappa[b * KK + k] = kp;
                out_kappa[b * KK + k] = kp;
            }
        }
    }
    // PDL: this block's dependent writes are done (incl. w zeroing above).
    __syncthreads();
    cudaTriggerProgrammaticLaunchCompletion();
}

// -------- Kernel 2 (phi + w reduce), PDL-overlapped with k_params --------
__global__ void __launch_bounds__(256)
k_w(const float4* __restrict__ oh,
    float* __restrict__ p_out,
    float* __restrict__ w) {
    __shared__ float sa[KK], sb[KK], sk[KK];
    __shared__ float s_phi[CHUNK];
    __shared__ float4 red[8][32];

    const int b = blockIdx.y;
    const int t0 = blockIdx.x * CHUNK;
    const int tid = threadIdx.x;

    // Wait for k_params' triggered completion before touching scratch.
    cudaGridDependencySynchronize();

    if (tid < KK) {
        sa[tid] = g_alpha[b * KK + tid];
        sb[tid] = g_beta[b * KK + tid];
        sk[tid] = g_kappa[b * KK + tid];
    }
    __syncthreads();

    {
        const float tf = (float)(t0 + tid);
        float s = 0.0f;
#pragma unroll
        for (int k = 0; k < KK; k++) {
            const float d = sk[k] - tf;
            s += sa[k] * __expf(-sb[k] * d * d);
        }
        s_phi[tid] = s;
        __stcs(p_out + b * TT + t0 + tid, s);
    }
    __syncthreads();

    const int q = tid & 31, r = tid >> 5;
    const float4* base = oh + (size_t)(b * TT + t0) * 32;  // 32 float4/row

    float4 acc = make_float4(0.f, 0.f, 0.f, 0.f);
#pragma unroll 8
    for (int i = 0; i < CHUNK / 8; i++) {
        const int idx = i * 256 + tid;           // row = i*8 + r, col = q
        const float4 o = __ldcs(base + idx);
        const float ph = s_phi[i * 8 + r];
        acc.x += ph * o.x;
        acc.y += ph * o.y;
        acc.z += ph * o.z;
        acc.w += ph * o.w;
    }

    red[r][q] = acc;
    __syncthreads();
    if (r < 4) {
        const float4 o = red[r + 4][q];
        acc.x += o.x; acc.y += o.y; acc.z += o.z; acc.w += o.w;
        red[r][q] = acc;
    }
    __syncthreads();
    if (r < 2) {
        const float4 o = red[r + 2][q];
        acc.x += o.x; acc.y += o.y; acc.z += o.z; acc.w += o.w;
        red[r][q] = acc;
    }
    __syncthreads();
    if (r == 0) {
        const float4 o = red[1][q];
        acc.x += o.x; acc.y += o.y; acc.z += o.z; acc.w += o.w;
        float* dst = w + b * VV + q * 4;
        atomicAdd(dst + 0, acc.x);
        atomicAdd(dst + 1, acc.y);
        atomicAdd(dst + 2, acc.z);
        atomicAdd(dst + 3, acc.w);
    }
}

extern "C" void kernel_launch(void* const* d_in, const int* in_sizes, int n_in,
                              void* d_out, int out_size) {
    const float* x        = (const float*)d_in[0];  // (B, C)
    const float* kap_old  = (const float*)d_in[1];  // (B, K)
    const float* onehots  = (const float*)d_in[2];  // (B, T, V)
    const float* W        = (const float*)d_in[3];  // (3K, C)
    const float* bias     = (const float*)d_in[4];  // (3K,)

    float* out   = (float*)d_out;
    float* w_out = out;                       // (B, V)
    float* k_out = out + BB * VV;             // (B, K)
    float* p_out = out + BB * VV + BB * KK;   // (B, T)

    k_params<<<(BB * 3 * KK) / 8, 256>>>(x, kap_old, W, bias, w_out, k_out);

    // k_w with programmatic dependent launch: overlap launch/preamble with
    // k_params; device-side cudaGridDependencySynchronize() enforces order.
    cudaLaunchConfig_t cfg = {};
    cfg.gridDim = dim3(TT / CHUNK, BB);
    cfg.blockDim = dim3(256);
    cudaLaunchAttribute attr[1];
    attr[0].id = cudaLaunchAttributeProgrammaticStreamSerialization;
    attr[0].val.programmaticStreamSerializationAllowed = 1;
    cfg.attrs = attr;
    cfg.numAttrs = 1;
    cudaLaunchKernelEx(&cfg, k_w, (const float4*)onehots, p_out, w_out);
}